// round 8
// baseline (speedup 1.0000x reference)
#include <cuda_runtime.h>

// QPIELayer: 16-qubit circuit reduced to a 10-qubit live state (8 system + 2
// ancilla) with incoherent 4-way branch splits at layer boundaries (records
// are write-once, read-once-as-control, traced by the diagonal measurement).
// Whole per-batch sim lives in shared memory. One CTA per batch element.
//
// Bit layout (amp index within a 1024-amp branch block):
//   bits 0..7  = system qubits 0..7
//   bit  8     = ancilla 0 (== record used by CCRX this layer)
//   bit  9     = ancilla 1
//   bits >=10  = branch id (dead record values from previous layers)

#define NTH 256
#define AMPS_MAX 16384            // 16 branches x 1024
#define B_OFF 16384               // region B starts here (4096 amps)
#define SMEM_BYTES ((AMPS_MAX + 4096) * (int)sizeof(float2))   // 163840

__device__ __forceinline__ float2 cmul(float2 a, float2 b) {
    return make_float2(a.x * b.x - a.y * b.y, a.x * b.y + a.y * b.x);
}
__device__ __forceinline__ float2 cconj(float2 a) { return make_float2(a.x, -a.y); }

// generic single-qubit gate on bit b
__device__ __forceinline__ void gate1(float2* st, int namp, int b,
                                      float2 u00, float2 u01, float2 u10, float2 u11) {
    const int np = namp >> 1;
    const int lomask = (1 << b) - 1;
    for (int p = threadIdx.x; p < np; p += NTH) {
        int i0 = ((p >> b) << (b + 1)) | (p & lomask);
        int i1 = i0 | (1 << b);
        float2 a = st[i0], c = st[i1];
        float2 n0 = make_float2(u00.x*a.x - u00.y*a.y + u01.x*c.x - u01.y*c.y,
                                u00.x*a.y + u00.y*a.x + u01.x*c.y + u01.y*c.x);
        float2 n1 = make_float2(u10.x*a.x - u10.y*a.y + u11.x*c.x - u11.y*c.y,
                                u10.x*a.y + u10.y*a.x + u11.x*c.y + u11.y*c.x);
        st[i0] = n0; st[i1] = n1;
    }
    __syncthreads();
}

// fused RZZ(t3)*RYY(t2)*RXX(t1) on bits b1<b2 (all three commute)
__device__ __forceinline__ void pairGate(float2* st, int namp, int b1, int b2,
                                         float t1, float t2, float t3) {
    float sd, cd, K2, L2;
    sincosf(0.5f * (t1 - t2), &sd, &cd);
    const float K = cd, L = -sd;               // {00,11} block: [[K, iL],[iL, K]]
    sincosf(0.5f * (t1 + t2), &L2, &K2);        // {01,10} block: [[K2,-iL2],[-iL2,K2]]
    float es, ec;
    sincosf(0.5f * t3, &es, &ec);
    const float2 e3 = make_float2(ec, -es);     // exp(-i t3/2) on {00,11}
    const float2 f3 = make_float2(ec,  es);     // conj on {01,10}

    const int nq = namp >> 2;
    const int m1 = (1 << b1) - 1, m2 = (1 << b2) - 1;
    for (int p = threadIdx.x; p < nq; p += NTH) {
        int t = ((p >> b1) << (b1 + 1)) | (p & m1);
        int i00 = ((t >> b2) << (b2 + 1)) | (t & m2);
        int i01 = i00 | (1 << b1);
        int i10 = i00 | (1 << b2);
        int i11 = i01 | (1 << b2);
        float2 a00 = st[i00], a01 = st[i01], a10 = st[i10], a11 = st[i11];
        float2 t00 = make_float2(K * a00.x - L * a11.y, K * a00.y + L * a11.x);
        float2 t11 = make_float2(K * a11.x - L * a00.y, K * a11.y + L * a00.x);
        float2 t01 = make_float2(K2 * a01.x + L2 * a10.y, K2 * a01.y - L2 * a10.x);
        float2 t10 = make_float2(K2 * a10.x + L2 * a01.y, K2 * a10.y - L2 * a01.x);
        st[i00] = cmul(e3, t00); st[i11] = cmul(e3, t11);
        st[i01] = cmul(f3, t01); st[i10] = cmul(f3, t10);
    }
    __syncthreads();
}

// CCRX(pi/4): controls on bits cr, cq = 1; RX on bit tq
__device__ __forceinline__ void ccrx(float2* st, int namp, int cr, int cq, int tq) {
    const float c = 0.92387953251128675613f;   // cos(pi/8)
    const float s = 0.38268343236508977173f;   // sin(pi/8)
    const int np = namp >> 1;
    const int lomask = (1 << tq) - 1;
    const int cmask = (1 << cr) | (1 << cq);
    for (int p = threadIdx.x; p < np; p += NTH) {
        int i0 = ((p >> tq) << (tq + 1)) | (p & lomask);
        if ((i0 & cmask) == cmask) {
            int i1 = i0 | (1 << tq);
            float2 a = st[i0], b = st[i1];
            st[i0] = make_float2(c * a.x + s * b.y, c * a.y - s * b.x);
            st[i1] = make_float2(c * b.x + s * a.y, c * b.y - s * a.x);
        }
    }
    __syncthreads();
}

__global__ void __launch_bounds__(NTH, 1)
qpie_kernel(const float* __restrict__ x, const float* __restrict__ w,
            const float* __restrict__ pw, float* __restrict__ out) {
    extern __shared__ float2 st[];
    __shared__ float co[4][8];        // CRZ diagonal phase coefs per anc pattern
    __shared__ float wsum[NTH / 32][8];

    const int bi = blockIdx.x;
    const int tid = threadIdx.x;
    const float R = 0.70710678118654752440f;   // 1/sqrt(2)

    // |0...0>
    for (int i = tid; i < 1024; i += NTH)
        st[i] = make_float2(i == 0 ? 1.0f : 0.0f, 0.0f);
    __syncthreads();

    float xs[8];
#pragma unroll
    for (int q = 0; q < 8; ++q) xs[q] = x[bi * 8 + q];

    float2* cur = st;
    int namp = 1024;

    for (int L = 0; L < 3; ++L) {
        const float* wl = w + L * 48;
        const float* pwl = pw + L * 16;

        // --- per-qubit rotation (RY even layers, RX odd); fold initial H into L0
        for (int q = 0; q < 8; ++q) {
            float s, c;
            sincosf(0.5f * xs[q], &s, &c);
            float2 u00, u01, u10, u11;
            if ((L & 1) == 0) {   // RY
                u00 = make_float2(c, 0); u01 = make_float2(-s, 0);
                u10 = make_float2(s, 0); u11 = make_float2(c, 0);
            } else {              // RX
                u00 = make_float2(c, 0); u01 = make_float2(0, -s);
                u10 = make_float2(0, -s); u11 = make_float2(c, 0);
            }
            if (L == 0) {  // U <- U @ H
                float2 v00 = make_float2(R * (u00.x + u01.x), R * (u00.y + u01.y));
                float2 v01 = make_float2(R * (u00.x - u01.x), R * (u00.y - u01.y));
                float2 v10 = make_float2(R * (u10.x + u11.x), R * (u10.y + u11.y));
                float2 v11 = make_float2(R * (u10.x - u11.x), R * (u10.y - u11.y));
                u00 = v00; u01 = v01; u10 = v10; u11 = v11;
            }
            gate1(cur, namp, q, u00, u01, u10, u11);
        }

        // --- H on both ancillas
        {
            float2 hr = make_float2(R, 0), hn = make_float2(-R, 0);
            gate1(cur, namp, 8, hr, hr, hr, hn);
            gate1(cur, namp, 9, hr, hr, hr, hn);
        }

        // --- all 16 CRZ gates as one diagonal pass
        if (tid < 32) {
            int m = tid >> 3, j = tid & 7;
            float c0 = (m & 1) ? pwl[j] : -pwl[j];
            float c1 = (m & 2) ? pwl[8 + j] : -pwl[8 + j];
            co[m][j] = 0.5f * (c0 + c1);
        }
        __syncthreads();
        for (int i = tid; i < namp; i += NTH) {
            const float* cf = co[(i >> 8) & 3];
            float phi = 0.0f;
#pragma unroll
            for (int j = 0; j < 8; ++j) phi += (float)((i >> j) & 1) * cf[j];
            float sp, cp;
            sincosf(phi, &sp, &cp);
            st_store:
            cur[i] = cmul(cur[i], make_float2(cp, sp));
        }
        __syncthreads();

        // --- odd layers: extra H on ancillas (pre-SWAP in reference)
        if (L & 1) {
            float2 hr = make_float2(R, 0), hn = make_float2(-R, 0);
            gate1(cur, namp, 8, hr, hr, hr, hn);
            gate1(cur, namp, 9, hr, hr, hr, hn);
        }

        // --- SWAP(anc, rec) elided: record == ancilla bit for this layer

        // --- entangling pairs + CCRX
        for (int i = 0; i < 4; ++i) {
            int q1 = 2 * i, q2 = 2 * i + 1;
            pairGate(cur, namp, q1, q2, wl[3 * i], wl[3 * i + 1], wl[3 * i + 2]);
            if (i < 2) ccrx(cur, namp, 8 + i, q1, q2);
        }
        for (int i = 0; i < 3; ++i) {
            int q1 = 2 * i + 1, q2 = 2 * i + 2, idx = 4 + i;
            pairGate(cur, namp, q1, q2, wl[3 * idx], wl[3 * idx + 1], wl[3 * idx + 2]);
        }

        // --- fused RZ*RY*RX per system qubit (vw block)
        for (int q = 0; q < 8; ++q) {
            float t1 = wl[24 + 3 * q], t2 = wl[25 + 3 * q], t3 = wl[26 + 3 * q];
            float s1, c1, s2, c2, es, ec;
            sincosf(0.5f * t1, &s1, &c1);
            sincosf(0.5f * t2, &s2, &c2);
            sincosf(0.5f * t3, &es, &ec);
            // Ry@Rx
            float2 a00 = make_float2(c1 * c2,  s1 * s2);
            float2 a01 = make_float2(-s2 * c1, -c2 * s1);
            float2 a10 = make_float2( s2 * c1, -c2 * s1);
            float2 a11 = make_float2(c1 * c2, -s1 * s2);
            float2 e = make_float2(ec, -es);       // exp(-i t3/2)
            float2 u00 = cmul(e, a00), u01 = cmul(e, a01);
            float2 u10 = cmul(cconj(e), a10), u11 = cmul(cconj(e), a11);
            gate1(cur, namp, q, u00, u01, u10, u11);
        }

        // --- layer boundary: trace dead ancillas -> 4x branch split, fresh |00> anc
        if (L == 0) {
            float2* B = st + B_OFF;
            for (int d = tid; d < 4096; d += NTH) {
                int a = d >> 10, s = d & 1023;
                B[d] = (s < 256) ? cur[a * 256 + s] : make_float2(0, 0);
            }
            __syncthreads();
            cur = B; namp = 4096;
        } else if (L == 1) {
            float2* A = st;
            for (int d = tid; d < 16384; d += NTH) {
                int n = d >> 10, s = d & 1023;
                int b = n >> 2, a = n & 3;
                A[d] = (s < 256) ? cur[b * 1024 + a * 256 + s] : make_float2(0, 0);
            }
            __syncthreads();
            cur = A; namp = 16384;
        }
    }

    // --- measurement: EV[q] = sum |amp|^2 * (1 - 2*bit_q), trace over anc+branches
    float acc[8];
#pragma unroll
    for (int q = 0; q < 8; ++q) acc[q] = 0.0f;
    for (int i = tid; i < 16384; i += NTH) {
        float2 a = cur[i];
        float p = a.x * a.x + a.y * a.y;
#pragma unroll
        for (int q = 0; q < 8; ++q) acc[q] += ((i >> q) & 1) ? -p : p;
    }
    const int wid = tid >> 5, lane = tid & 31;
#pragma unroll
    for (int q = 0; q < 8; ++q) {
        float v = acc[q];
#pragma unroll
        for (int o = 16; o > 0; o >>= 1) v += __shfl_down_sync(0xffffffffu, v, o);
        if (lane == 0) wsum[wid][q] = v;
    }
    __syncthreads();
    if (tid < 8) {
        float s = 0.0f;
#pragma unroll
        for (int wgi = 0; wgi < NTH / 32; ++wgi) s += wsum[wgi][tid];
        out[bi * 8 + tid] = s;
    }
}

extern "C" void kernel_launch(void* const* d_in, const int* in_sizes, int n_in,
                              void* d_out, int out_size) {
    const float* x  = (const float*)d_in[0];   // (16, 8)
    const float* w  = (const float*)d_in[1];   // (3, 48)
    const float* pw = (const float*)d_in[2];   // (3, 2, 8)
    float* out = (float*)d_out;                // (16, 8)
    (void)in_sizes; (void)n_in; (void)out_size;

    cudaFuncSetAttribute(qpie_kernel, cudaFuncAttributeMaxDynamicSharedMemorySize,
                         SMEM_BYTES);
    qpie_kernel<<<16, NTH, SMEM_BYTES>>>(x, w, pw, out);
}

// round 11
// speedup vs baseline: 4.2580x; 4.2580x over previous
#include <cuda_runtime.h>

// QPIELayer multi-kernel pipeline. 16-qubit circuit reduced to 10 live qubits
// (8 system + 2 ancilla); records are write-once/read-once-as-control and
// traced by the diagonal measurement, so each layer boundary is an incoherent
// 4-way branch split. Branches are independent -> one CTA per (batch, branch):
//   K1: grid 16  (batch)             layer 0 on 1024 amps
//   K2: grid 64  (batch x 4 branch)  layer 1
//   K3: grid 256 (batch x 16 branch) layer 2 + per-branch EV partials
//   K4: grid 16  branch-sum reduce -> out
// State = 1024 float2 in shared memory, XOR-swizzled to kill bank conflicts.

#define NTH 256

__device__ float2 g_s1[16 * 1024];    // after layer 0 (per batch, 4 branches x 256)
__device__ float2 g_s2[64 * 1024];    // after layer 1
__device__ float  g_ev[256 * 8];      // per (batch,branch) EV partials

__device__ __forceinline__ int IDX(int i) { return i ^ ((i >> 5) & 31); }

__device__ __forceinline__ float2 cmul(float2 a, float2 b) {
    return make_float2(a.x * b.x - a.y * b.y, a.x * b.y + a.y * b.x);
}
__device__ __forceinline__ float2 cmac(float2 a, float2 b, float2 c) {   // a*b + c
    return make_float2(fmaf(a.x, b.x, fmaf(-a.y, b.y, c.x)),
                       fmaf(a.x, b.y, fmaf( a.y, b.x, c.y)));
}
__device__ __forceinline__ float2 cconj(float2 a) { return make_float2(a.x, -a.y); }
__device__ __forceinline__ float2 cadd(float2 a, float2 b) { return make_float2(a.x + b.x, a.y + b.y); }
__device__ __forceinline__ float2 csub(float2 a, float2 b) { return make_float2(a.x - b.x, a.y - b.y); }
__device__ __forceinline__ float2 chalf(float2 a) { return make_float2(0.5f * a.x, 0.5f * a.y); }

// ---- fused two-single-qubit-gates pass: U_b2 (x) U_b1 on quads -------------
template<int B1, int B2>
__device__ __forceinline__ void gate2(float2* st, const float2* Ua, const float2* Ub) {
    const int p = threadIdx.x;                       // exactly 256 quads
    const int m1 = (1 << B1) - 1, m2 = (1 << B2) - 1;
    int t   = ((p >> B1) << (B1 + 1)) | (p & m1);
    int i00 = ((t >> B2) << (B2 + 1)) | (t & m2);
    int i01 = i00 | (1 << B1), i10 = i00 | (1 << B2), i11 = i01 | (1 << B2);
    float2 x00 = st[IDX(i00)], x01 = st[IDX(i01)];
    float2 x10 = st[IDX(i10)], x11 = st[IDX(i11)];
    // Ua along B1
    float2 y00 = cmac(Ua[0], x00, cmul(Ua[1], x01));
    float2 y01 = cmac(Ua[2], x00, cmul(Ua[3], x01));
    float2 y10 = cmac(Ua[0], x10, cmul(Ua[1], x11));
    float2 y11 = cmac(Ua[2], x10, cmul(Ua[3], x11));
    // Ub along B2
    float2 z00 = cmac(Ub[0], y00, cmul(Ub[1], y10));
    float2 z10 = cmac(Ub[2], y00, cmul(Ub[3], y10));
    float2 z01 = cmac(Ub[0], y01, cmul(Ub[1], y11));
    float2 z11 = cmac(Ub[2], y01, cmul(Ub[3], y11));
    st[IDX(i00)] = z00; st[IDX(i01)] = z01; st[IDX(i10)] = z10; st[IDX(i11)] = z11;
    __syncthreads();
}

// ---- fused RZZ*RYY*RXX on (B1,B2), optionally followed by CCRX(anc=CC, B1, B2)
template<int B1, int B2, int CC>
__device__ __forceinline__ void pairGate(float2* st, const float* pc) {
    const float K = pc[0], Lc = pc[1], K2 = pc[2], L2 = pc[3], ec = pc[4], es = pc[5];
    const float2 e3 = make_float2(ec, -es), f3 = make_float2(ec, es);
    const int p = threadIdx.x;
    const int m1 = (1 << B1) - 1, m2 = (1 << B2) - 1;
    int t   = ((p >> B1) << (B1 + 1)) | (p & m1);
    int i00 = ((t >> B2) << (B2 + 1)) | (t & m2);
    int i01 = i00 | (1 << B1), i10 = i00 | (1 << B2), i11 = i01 | (1 << B2);
    float2 a00 = st[IDX(i00)], a01 = st[IDX(i01)];
    float2 a10 = st[IDX(i10)], a11 = st[IDX(i11)];
    float2 t00 = make_float2(K * a00.x - Lc * a11.y, K * a00.y + Lc * a11.x);
    float2 t11 = make_float2(K * a11.x - Lc * a00.y, K * a11.y + Lc * a00.x);
    float2 t01 = make_float2(K2 * a01.x + L2 * a10.y, K2 * a01.y - L2 * a10.x);
    float2 t10 = make_float2(K2 * a10.x + L2 * a01.y, K2 * a10.y - L2 * a01.x);
    float2 o00 = cmul(e3, t00), o11 = cmul(e3, t11);
    float2 o01 = cmul(f3, t01), o10 = cmul(f3, t10);
    if (CC >= 0 && ((i00 >> CC) & 1)) {
        const float cc = 0.92387953251128675613f;   // cos(pi/8)
        const float ss = 0.38268343236508977173f;   // sin(pi/8)
        float2 n01 = make_float2(cc * o01.x + ss * o11.y, cc * o01.y - ss * o11.x);
        float2 n11 = make_float2(cc * o11.x + ss * o01.y, cc * o11.y - ss * o01.x);
        o01 = n01; o11 = n11;
    }
    st[IDX(i00)] = o00; st[IDX(i01)] = o01; st[IDX(i10)] = o10; st[IDX(i11)] = o11;
    __syncthreads();
}

// ---- fused ancilla block: (H(x)H) then CRZ diagonal (then H(x)H if ODD) ----
template<int ODD>
__device__ __forceinline__ void ancBlock(float2* st, const float* pwh) {
    const int s = threadIdx.x;                       // 256 system states
    float2 x0 = st[IDX(s)],       x1 = st[IDX(s + 256)];
    float2 x2 = st[IDX(s + 512)], x3 = st[IDX(s + 768)];
    float2 v0 = chalf(cadd(cadd(x0, x1), cadd(x2, x3)));
    float2 v1 = chalf(cadd(csub(x0, x1), csub(x2, x3)));
    float2 v2 = chalf(csub(cadd(x0, x1), cadd(x2, x3)));
    float2 v3 = chalf(cadd(csub(x0, x1), csub(x3, x2)));
    float d0 = 0.0f, d1 = 0.0f;
#pragma unroll
    for (int j = 0; j < 8; ++j)
        if ((s >> j) & 1) { d0 += pwh[j]; d1 += pwh[8 + j]; }
    float sp, cp, sm, cm;
    sincosf(d0 + d1, &sp, &cp);
    sincosf(d0 - d1, &sm, &cm);
    float2 P = make_float2(cp, sp), M = make_float2(cm, sm);
    float2 w0 = cmul(cconj(P), v0);
    float2 w1 = cmul(M,        v1);
    float2 w2 = cmul(cconj(M), v2);
    float2 w3 = cmul(P,        v3);
    if (ODD) {
        float2 y0 = chalf(cadd(cadd(w0, w1), cadd(w2, w3)));
        float2 y1 = chalf(cadd(csub(w0, w1), csub(w2, w3)));
        float2 y2 = chalf(csub(cadd(w0, w1), cadd(w2, w3)));
        float2 y3 = chalf(cadd(csub(w0, w1), csub(w3, w2)));
        w0 = y0; w1 = y1; w2 = y2; w3 = y3;
    }
    st[IDX(s)] = w0; st[IDX(s + 256)] = w1; st[IDX(s + 512)] = w2; st[IDX(s + 768)] = w3;
    __syncthreads();
}

// ---- one full layer on a 1024-amp state --------------------------------------
template<int L>
__device__ __forceinline__ void simLayer(float2* st, const float* x, int batch,
                                         const float* w, const float* pw,
                                         float2 (*rotU)[4], float2 (*vwU)[4],
                                         float (*pco)[6], float* pwh) {
    const float* wl  = w  + L * 48;
    const float* pwl = pw + L * 16;
    const int tid = threadIdx.x;
    const float R = 0.70710678118654752440f;

    // one warp precomputes all per-layer gate constants into shared
    if (tid < 8) {                                   // per-qubit rot (RY even / RX odd)
        float s, c;
        sincosf(0.5f * x[batch * 8 + tid], &s, &c);
        float2 u00, u01, u10, u11;
        if ((L & 1) == 0) {
            u00 = make_float2(c, 0); u01 = make_float2(-s, 0);
            u10 = make_float2(s, 0); u11 = make_float2(c, 0);
        } else {
            u00 = make_float2(c, 0); u01 = make_float2(0, -s);
            u10 = make_float2(0, -s); u11 = make_float2(c, 0);
        }
        if (L == 0) {   // fold initial H: U <- U @ H
            float2 v00 = make_float2(R * (u00.x + u01.x), R * (u00.y + u01.y));
            float2 v01 = make_float2(R * (u00.x - u01.x), R * (u00.y - u01.y));
            float2 v10 = make_float2(R * (u10.x + u11.x), R * (u10.y + u11.y));
            float2 v11 = make_float2(R * (u10.x - u11.x), R * (u10.y - u11.y));
            u00 = v00; u01 = v01; u10 = v10; u11 = v11;
        }
        rotU[tid][0] = u00; rotU[tid][1] = u01; rotU[tid][2] = u10; rotU[tid][3] = u11;
    } else if (tid < 16) {                           // fused RZ*RY*RX (vw block)
        int q = tid - 8;
        float t1 = wl[24 + 3 * q], t2 = wl[25 + 3 * q], t3 = wl[26 + 3 * q];
        float s1, c1, s2, c2, es, ec;
        sincosf(0.5f * t1, &s1, &c1);
        sincosf(0.5f * t2, &s2, &c2);
        sincosf(0.5f * t3, &es, &ec);
        float2 a00 = make_float2(c1 * c2,  s1 * s2);
        float2 a01 = make_float2(-s2 * c1, -c2 * s1);
        float2 a10 = make_float2( s2 * c1, -c2 * s1);
        float2 a11 = make_float2(c1 * c2, -s1 * s2);
        float2 e = make_float2(ec, -es);
        vwU[q][0] = cmul(e, a00); vwU[q][1] = cmul(e, a01);
        vwU[q][2] = cmul(cconj(e), a10); vwU[q][3] = cmul(cconj(e), a11);
    } else if (tid < 23) {                           // pair-gate coefficients
        int i = tid - 16;
        float t1 = wl[3 * i], t2 = wl[3 * i + 1], t3 = wl[3 * i + 2];
        float sd, cd, s2, c2, es, ec;
        sincosf(0.5f * (t1 - t2), &sd, &cd);
        sincosf(0.5f * (t1 + t2), &s2, &c2);
        sincosf(0.5f * t3, &es, &ec);
        pco[i][0] = cd; pco[i][1] = -sd; pco[i][2] = c2; pco[i][3] = s2;
        pco[i][4] = ec; pco[i][5] = es;
    } else if (tid >= 32 && tid < 48) {
        pwh[tid - 32] = 0.5f * pwl[tid - 32];
    }
    __syncthreads();

    gate2<0, 1>(st, rotU[0], rotU[1]);
    gate2<2, 3>(st, rotU[2], rotU[3]);
    gate2<4, 5>(st, rotU[4], rotU[5]);
    gate2<6, 7>(st, rotU[6], rotU[7]);
    ancBlock<(L & 1)>(st, pwh);
    pairGate<0, 1, 8>(st, pco[0]);
    pairGate<2, 3, 9>(st, pco[1]);
    pairGate<4, 5, -1>(st, pco[2]);
    pairGate<6, 7, -1>(st, pco[3]);
    pairGate<1, 2, -1>(st, pco[4]);
    pairGate<3, 4, -1>(st, pco[5]);
    pairGate<5, 6, -1>(st, pco[6]);
    gate2<0, 1>(st, vwU[0], vwU[1]);
    gate2<2, 3>(st, vwU[2], vwU[3]);
    gate2<4, 5>(st, vwU[4], vwU[5]);
    gate2<6, 7>(st, vwU[6], vwU[7]);
}

#define SIM_SHARED \
    __shared__ float2 st[1024]; \
    __shared__ float2 rotU[8][4]; \
    __shared__ float2 vwU[8][4]; \
    __shared__ float  pco[7][6]; \
    __shared__ float  pwh[16];

__global__ void __launch_bounds__(NTH)
k_layer0(const float* __restrict__ x, const float* __restrict__ w,
         const float* __restrict__ pw) {
    SIM_SHARED
    const int bi = blockIdx.x, tid = threadIdx.x;
    for (int i = tid; i < 1024; i += NTH)
        st[i] = make_float2(i == 0 ? 1.0f : 0.0f, 0.0f);     // IDX(0)==0
    simLayer<0>(st, x, bi, w, pw, rotU, vwU, pco, pwh);
    for (int i = tid; i < 1024; i += NTH)
        g_s1[bi * 1024 + i] = st[IDX(i)];
}

__global__ void __launch_bounds__(NTH)
k_layer1(const float* __restrict__ x, const float* __restrict__ w,
         const float* __restrict__ pw) {
    SIM_SHARED
    const int blk = blockIdx.x, tid = threadIdx.x;
    const int batch = blk >> 2, br = blk & 3;
    for (int i = tid; i < 1024; i += NTH) {
        float2 v = (i < 256) ? g_s1[batch * 1024 + br * 256 + i] : make_float2(0, 0);
        st[IDX(i)] = v;
    }
    simLayer<1>(st, x, batch, w, pw, rotU, vwU, pco, pwh);
    for (int i = tid; i < 1024; i += NTH)
        g_s2[blk * 1024 + i] = st[IDX(i)];
}

__global__ void __launch_bounds__(NTH)
k_layer2(const float* __restrict__ x, const float* __restrict__ w,
         const float* __restrict__ pw) {
    SIM_SHARED
    __shared__ float wsum[NTH / 32][8];
    const int blk = blockIdx.x, tid = threadIdx.x;
    const int batch = blk >> 4, br1 = (blk >> 2) & 3, br2 = blk & 3;
    for (int i = tid; i < 1024; i += NTH) {
        float2 v = (i < 256) ? g_s2[(batch * 4 + br1) * 1024 + br2 * 256 + i]
                             : make_float2(0, 0);
        st[IDX(i)] = v;
    }
    simLayer<2>(st, x, batch, w, pw, rotU, vwU, pco, pwh);

    // per-branch EV partials (trace over anc bits 8,9; Z-signs on bits 0..7)
    float acc[8];
#pragma unroll
    for (int q = 0; q < 8; ++q) acc[q] = 0.0f;
    for (int i = tid; i < 1024; i += NTH) {
        float2 a = st[IDX(i)];
        float p = a.x * a.x + a.y * a.y;
#pragma unroll
        for (int q = 0; q < 8; ++q) acc[q] += ((i >> q) & 1) ? -p : p;
    }
    const int wid = tid >> 5, lane = tid & 31;
#pragma unroll
    for (int q = 0; q < 8; ++q) {
        float v = acc[q];
#pragma unroll
        for (int o = 16; o > 0; o >>= 1) v += __shfl_down_sync(0xffffffffu, v, o);
        if (lane == 0) wsum[wid][q] = v;
    }
    __syncthreads();
    if (tid < 8) {
        float s = 0.0f;
#pragma unroll
        for (int wgi = 0; wgi < NTH / 32; ++wgi) s += wsum[wgi][tid];
        g_ev[blk * 8 + tid] = s;
    }
}

__global__ void __launch_bounds__(32)
k_reduce(float* __restrict__ out) {
    const int bi = blockIdx.x, tid = threadIdx.x;
    if (tid < 8) {
        float s = 0.0f;
#pragma unroll
        for (int k = 0; k < 16; ++k) s += g_ev[(bi * 16 + k) * 8 + tid];
        out[bi * 8 + tid] = s;
    }
}

extern "C" void kernel_launch(void* const* d_in, const int* in_sizes, int n_in,
                              void* d_out, int out_size) {
    const float* x  = (const float*)d_in[0];   // (16, 8)
    const float* w  = (const float*)d_in[1];   // (3, 48)
    const float* pw = (const float*)d_in[2];   // (3, 2, 8)
    float* out = (float*)d_out;                // (16, 8)
    (void)in_sizes; (void)n_in; (void)out_size;

    k_layer0<<<16,  NTH>>>(x, w, pw);
    k_layer1<<<64,  NTH>>>(x, w, pw);
    k_layer2<<<256, NTH>>>(x, w, pw);
    k_reduce<<<16,  32>>>(out);
}